// round 13
// baseline (speedup 1.0000x reference)
#include <cuda_runtime.h>
#include <cuda_bf16.h>
#include <math.h>
#include <stdint.h>

#define NBANDS 160
#define NROWS  96
#define TLEN   2048
#define HALF_T 1024
#define NTRIL  4560   // 96*95/2

// ---------------- scratch (static device globals; no allocation) ----------------
__device__ float  g_xc[(size_t)NBANDS * NROWS * TLEN];    // centered rows (fp32)
__device__ double g_norm2[(size_t)NBANDS * NROWS];        // ||Xc||^2 (exact via df)
__device__ float  g_C[(size_t)NBANDS * NROWS * NROWS];    // correlation matrices
__device__ float  g_feat[(size_t)NBANDS * 5 * NROWS];     // per-row 5 features
__device__ float2 g_tw[HALF_T];                           // exp(-2*pi*i*k/2048)

// ---------------- two-float compensated add (fp32 pipe only) ----------------
__device__ __forceinline__ void twosum_acc(float& hi, float& lo, float a) {
    float s  = hi + a;
    float bb = s - hi;
    float e  = (hi - (s - bb)) + (a - bb);
    hi = s; lo += e;
}

// ---------------- generic fp32 block reduce ----------------
__device__ __forceinline__ float blockReduceSum(float val, float* red) {
    __syncthreads();
    int lane = threadIdx.x & 31, wid = threadIdx.x >> 5;
    #pragma unroll
    for (int o = 16; o > 0; o >>= 1) val += __shfl_xor_sync(0xffffffffu, val, o);
    if (lane == 0) red[wid] = val;
    __syncthreads();
    if (wid == 0) {
        int nw = (blockDim.x + 31) >> 5;
        float v = (lane < nw) ? red[lane] : 0.f;
        #pragma unroll
        for (int o = 16; o > 0; o >>= 1) v += __shfl_xor_sync(0xffffffffu, v, o);
        if (lane == 0) red[0] = v;
    }
    __syncthreads();
    return red[0];
}

// ---------------- batched fp32 reductions for stats kernel (256 thr, 8 warps) ----------------
__device__ __forceinline__ void red4f(float& a, float& b, float& c, float& d, float* buf) {
    int lane = threadIdx.x & 31, wid = threadIdx.x >> 5;
    #pragma unroll
    for (int o = 16; o > 0; o >>= 1) {
        a += __shfl_xor_sync(0xffffffffu, a, o);
        b += __shfl_xor_sync(0xffffffffu, b, o);
        c += __shfl_xor_sync(0xffffffffu, c, o);
        d += __shfl_xor_sync(0xffffffffu, d, o);
    }
    if (lane == 0) { buf[wid*4+0]=a; buf[wid*4+1]=b; buf[wid*4+2]=c; buf[wid*4+3]=d; }
    __syncthreads();
    if (threadIdx.x == 0) {
        float ta=0, tb=0, tc=0, td=0;
        #pragma unroll
        for (int w = 0; w < 8; w++) { ta+=buf[w*4+0]; tb+=buf[w*4+1]; tc+=buf[w*4+2]; td+=buf[w*4+3]; }
        buf[0]=ta; buf[1]=tb; buf[2]=tc; buf[3]=td;
    }
    __syncthreads();
    a=buf[0]; b=buf[1]; c=buf[2]; d=buf[3];
    __syncthreads();
}

__device__ __forceinline__ void red2f(float& a, float& b, float* buf) {
    int lane = threadIdx.x & 31, wid = threadIdx.x >> 5;
    #pragma unroll
    for (int o = 16; o > 0; o >>= 1) {
        a += __shfl_xor_sync(0xffffffffu, a, o);
        b += __shfl_xor_sync(0xffffffffu, b, o);
    }
    if (lane == 0) { buf[wid*2+0]=a; buf[wid*2+1]=b; }
    __syncthreads();
    if (threadIdx.x == 0) {
        float ta=0, tb=0;
        #pragma unroll
        for (int w = 0; w < 8; w++) { ta+=buf[w*2+0]; tb+=buf[w*2+1]; }
        buf[0]=ta; buf[1]=tb;
    }
    __syncthreads();
    a=buf[0]; b=buf[1];
    __syncthreads();
}

__device__ __forceinline__ void redmax2f(float& a, float& b, float* buf) {
    int lane = threadIdx.x & 31, wid = threadIdx.x >> 5;
    #pragma unroll
    for (int o = 16; o > 0; o >>= 1) {
        a = fmaxf(a, __shfl_xor_sync(0xffffffffu, a, o));
        b = fmaxf(b, __shfl_xor_sync(0xffffffffu, b, o));
    }
    if (lane == 0) { buf[wid*2+0]=a; buf[wid*2+1]=b; }
    __syncthreads();
    if (threadIdx.x == 0) {
        float ta=-INFINITY, tb=-INFINITY;
        #pragma unroll
        for (int w = 0; w < 8; w++) { ta=fmaxf(ta,buf[w*2+0]); tb=fmaxf(tb,buf[w*2+1]); }
        buf[0]=ta; buf[1]=tb;
    }
    __syncthreads();
    a=buf[0]; b=buf[1];
    __syncthreads();
}

// df (two-float) reduce for two accumulators
__device__ __forceinline__ void red2df(float& ahi, float& alo, float& bhi, float& blo, float* buf) {
    int lane = threadIdx.x & 31, wid = threadIdx.x >> 5;
    #pragma unroll
    for (int o = 16; o > 0; o >>= 1) {
        float ohi = __shfl_xor_sync(0xffffffffu, ahi, o);
        float olo = __shfl_xor_sync(0xffffffffu, alo, o);
        float s = ahi + ohi; float bb = s - ahi;
        float e = (ahi - (s - bb)) + (ohi - bb);
        alo = alo + olo + e; ahi = s;
        ohi = __shfl_xor_sync(0xffffffffu, bhi, o);
        olo = __shfl_xor_sync(0xffffffffu, blo, o);
        s = bhi + ohi; bb = s - bhi;
        e = (bhi - (s - bb)) + (ohi - bb);
        blo = blo + olo + e; bhi = s;
    }
    if (lane == 0) { buf[wid*4+0]=ahi; buf[wid*4+1]=alo; buf[wid*4+2]=bhi; buf[wid*4+3]=blo; }
    __syncthreads();
    if (threadIdx.x == 0) {
        float thi=0, tlo=0;
        #pragma unroll
        for (int w = 0; w < 8; w++) { twosum_acc(thi, tlo, buf[w*4+0]); tlo += buf[w*4+1]; }
        buf[0]=thi; buf[1]=tlo;
        thi=0; tlo=0;
        #pragma unroll
        for (int w = 0; w < 8; w++) { twosum_acc(thi, tlo, buf[w*4+2]); tlo += buf[w*4+3]; }
        buf[2]=thi; buf[3]=tlo;
    }
    __syncthreads();
    ahi=buf[0]; alo=buf[1]; bhi=buf[2]; blo=buf[3];
    __syncthreads();
}

// ---------------- kernel 0: twiddle table + profiling shims ----------------
__global__ void init_tw_kernel() {
    int k = blockIdx.x * 256 + threadIdx.x;
    if (k < HALF_T) {
        float sv, cv;
        sincospif(-(float)k / 1024.0f, &sv, &cv);
        g_tw[k] = make_float2(cv, sv);
    }
}
// no-op shims to shift ncu's -s 5 capture window onto stats_fft_kernel
__global__ void noop_kernel() {}

// ---------------- kernel 1: stats + center + packed 2-row Stockham FFT ----------------
// grid (48, 160), block 256. Stages 0+1+2 fused in registers (radix-8 front-end,
// padded smem layout phys = idx + (idx>>5)); stages 4..9 in smem; stage 10 fused
// into the unpack. Stage 3 reads the padded layout (conflict-free), writes unpadded.
__global__ void stats_fft_kernel(const float* __restrict__ wc) {
    const int rp = blockIdx.x;
    const int band = blockIdx.y;
    const int b = band / 5, nb = band % 5;
    const int r0 = 2 * rp, r1 = r0 + 1;
    const float* __restrict__ x = wc + (((size_t)b * NROWS + r0) * 5 + nb) * TLEN;
    const float* __restrict__ y = wc + (((size_t)b * NROWS + r1) * 5 + nb) * TLEN;

    __shared__ float2 bufA[TLEN + 64];   // padded for radix-8 front-end output
    __shared__ float2 bufB[TLEN];
    __shared__ float2 stw[HALF_T];
    __shared__ float  redf[32];

    const int tid = threadIdx.x;

    // copy twiddles to smem (ordered before first use by the sync inside red4f)
    #pragma unroll
    for (int i = 0; i < 4; i++) stw[tid + 256 * i] = g_tw[tid + 256 * i];

    float vx[8], vy[8];
    float sx = 0.f, sqx = 0.f, sy = 0.f, sqy = 0.f;
    float mxx = 0.f, mxy = 0.f;
    #pragma unroll
    for (int k = 0; k < 8; k++) {
        float a = x[tid + 256 * k];
        float c = y[tid + 256 * k];
        vx[k] = a; vy[k] = c;
        sx += a; sqx = fmaf(a, a, sqx); mxx = fmaxf(mxx, fabsf(a));
        sy += c; sqy = fmaf(c, c, sqy); mxy = fmaxf(mxy, fabsf(c));
    }

    // ---- fused FFT stages 0 + 1 + 2 (radix-8) entirely in registers ----
    // stage 0 (w=1): A_m = u+v, B_m = u-v for t_m = tid+256m (m=0..3)
    // stage 1 (w in {1,-i}): P_k at 4tid+k, Q_k at 4tid+1024+k
    // stage 2 (w_k = tw[256k]): R_k = P_k + w_k Q_k at 8tid+k; S_k = P_k - w_k Q_k at 8tid+4+k
    {
        float2 A0 = make_float2(vx[0] + vx[4], vy[0] + vy[4]);
        float2 A1 = make_float2(vx[1] + vx[5], vy[1] + vy[5]);
        float2 A2 = make_float2(vx[2] + vx[6], vy[2] + vy[6]);
        float2 A3 = make_float2(vx[3] + vx[7], vy[3] + vy[7]);
        float2 B0 = make_float2(vx[0] - vx[4], vy[0] - vy[4]);
        float2 B1 = make_float2(vx[1] - vx[5], vy[1] - vy[5]);
        float2 B2 = make_float2(vx[2] - vx[6], vy[2] - vy[6]);
        float2 B3 = make_float2(vx[3] - vx[7], vy[3] - vy[7]);
        // (-i)*(r,i) = (i,-r)
        float2 nB2 = make_float2(B2.y, -B2.x);
        float2 nB3 = make_float2(B3.y, -B3.x);
        float2 P0 = make_float2(A0.x + A2.x,  A0.y + A2.y);
        float2 P2 = make_float2(A0.x - A2.x,  A0.y - A2.y);
        float2 P1 = make_float2(B0.x + nB2.x, B0.y + nB2.y);
        float2 P3 = make_float2(B0.x - nB2.x, B0.y - nB2.y);
        float2 Q0 = make_float2(A1.x + A3.x,  A1.y + A3.y);
        float2 Q2 = make_float2(A1.x - A3.x,  A1.y - A3.y);
        float2 Q1 = make_float2(B1.x + nB3.x, B1.y + nB3.y);
        float2 Q3 = make_float2(B1.x - nB3.x, B1.y - nB3.y);
        const float S2 = 0.70710678118654752440f;
        // w1 = (S2,-S2); w2 = (0,-1); w3 = (-S2,-S2)
        float2 W1q = make_float2(Q1.x * S2 + Q1.y * S2,  Q1.y * S2 - Q1.x * S2);
        float2 W2q = make_float2(Q2.y, -Q2.x);
        float2 W3q = make_float2(-Q3.x * S2 + Q3.y * S2, -Q3.y * S2 - Q3.x * S2);
        int base = 8 * tid + (tid >> 2);        // padded: idx + (idx>>5), idx = 8*tid
        bufA[base + 0] = make_float2(P0.x + Q0.x,  P0.y + Q0.y);
        bufA[base + 4] = make_float2(P0.x - Q0.x,  P0.y - Q0.y);
        bufA[base + 1] = make_float2(P1.x + W1q.x, P1.y + W1q.y);
        bufA[base + 5] = make_float2(P1.x - W1q.x, P1.y - W1q.y);
        bufA[base + 2] = make_float2(P2.x + W2q.x, P2.y + W2q.y);
        bufA[base + 6] = make_float2(P2.x - W2q.x, P2.y - W2q.y);
        bufA[base + 3] = make_float2(P3.x + W3q.x, P3.y + W3q.y);
        bufA[base + 7] = make_float2(P3.x - W3q.x, P3.y - W3q.y);
    }

    red4f(sx, sy, sqx, sqy, redf);
    redmax2f(mxx, mxy, redf);
    float meanx = sx / (float)TLEN;
    float meany = sy / (float)TLEN;

    float nxh = 0.f, nxl = 0.f, nyh = 0.f, nyl = 0.f;
    float cx[8], cy[8];
    #pragma unroll
    for (int k = 0; k < 8; k++) {
        cx[k] = vx[k] - meanx; twosum_acc(nxh, nxl, cx[k] * cx[k]);
        cy[k] = vy[k] - meany; twosum_acc(nyh, nyl, cy[k] * cy[k]);
    }
    red2df(nxh, nxl, nyh, nyl, redf);

    float* __restrict__ xc0 = g_xc + ((size_t)band * NROWS + r0) * TLEN;
    float* __restrict__ xc1 = g_xc + ((size_t)band * NROWS + r1) * TLEN;
    #pragma unroll
    for (int k = 0; k < 8; k++) {
        xc0[tid + 256 * k] = cx[k];
        xc1[tid + 256 * k] = cy[k];
    }
    if (tid == 0) {
        double n2x = (double)nxh + (double)nxl;
        double n2y = (double)nyh + (double)nyl;
        g_norm2[(size_t)band * NROWS + r0] = n2x;
        g_norm2[(size_t)band * NROWS + r1] = n2y;
        float* f = g_feat + (size_t)band * 5 * NROWS;
        f[0 * NROWS + r0] = meanx;
        f[1 * NROWS + r0] = (float)sqrt(n2x / (double)(TLEN - 1));
        f[2 * NROWS + r0] = sqx;
        f[3 * NROWS + r0] = mxx;
        f[0 * NROWS + r1] = meany;
        f[1 * NROWS + r1] = (float)sqrt(n2y / (double)(TLEN - 1));
        f[2 * NROWS + r1] = sqy;
        f[3 * NROWS + r1] = mxy;
    }

    // ---- stage 3 (l=8): read padded bufA, write bufB ----
    __syncthreads();
    #pragma unroll
    for (int ti = 0; ti < 4; ti++) {
        int t = tid + 256 * ti;
        int j = t & 7;
        int i = t >> 3;
        float2 u = bufA[t + (t >> 5)];
        float2 v = bufA[t + 1056 + (t >> 5)];       // (t+1024) + ((t+1024)>>5)
        float2 w = stw[j << 7];
        float vr = v.x * w.x - v.y * w.y;
        float vi = v.x * w.y + v.y * w.x;
        int o = t + i * 8;
        bufB[o]     = make_float2(u.x + vr, u.y + vi);
        bufB[o + 8] = make_float2(u.x - vr, u.y - vi);
    }

    // ---- Stockham radix-2 stages s = 4..9 (unpadded ping-pong) ----
    float2* src = bufB;
    float2* dst = bufA;
    #pragma unroll 1
    for (int s = 4; s <= 9; s++) {
        const int l = 1 << s;
        __syncthreads();
        #pragma unroll
        for (int ti = 0; ti < 4; ti++) {
            int t = tid + 256 * ti;
            int j = t & (l - 1);
            int i = t >> s;
            float2 u = src[t];
            float2 v = src[t + HALF_T];
            float2 w = stw[j << (10 - s)];
            float vr = v.x * w.x - v.y * w.y;
            float vi = v.x * w.y + v.y * w.x;
            int o = t + i * l;
            dst[o]     = make_float2(u.x + vr, u.y + vi);
            dst[o + l] = make_float2(u.x - vr, u.y - vi);
        }
        float2* tmp = src; src = dst; dst = tmp;
    }
    __syncthreads();
    // after 6 stages (even number of swaps), final data sits in bufB == src

    // ---- fused final stage (s=10) + unpack two real spectra ----
    float psx = 0.f, psy = 0.f;
    float pxv[4], pyv[4];
    #pragma unroll
    for (int ki = 0; ki < 4; ki++) {
        int k = tid + 256 * ki;
        float2 u = src[k];
        float2 v = src[k + 1024];
        float2 w = stw[k];
        float vr = v.x * w.x - v.y * w.y;
        float vi = v.x * w.y + v.y * w.x;
        float2 Zk = make_float2(u.x + vr, u.y + vi);
        float2 Zn;
        if (k == 0) {
            Zn = Zk;
        } else {
            int m = 1024 - k;
            float2 u2 = src[m];
            float2 v2 = src[m + 1024];
            float2 w2 = stw[m];
            float vr2 = v2.x * w2.x - v2.y * w2.y;
            float vi2 = v2.x * w2.y + v2.y * w2.x;
            Zn = make_float2(u2.x - vr2, u2.y - vi2);
        }
        float Xr = 0.5f * (Zk.x + Zn.x);
        float Xi = 0.5f * (Zk.y - Zn.y);
        float Yr = 0.5f * (Zk.y + Zn.y);
        float Yi = 0.5f * (Zn.x - Zk.x);
        float px = Xr * Xr + Xi * Xi;
        float py = Yr * Yr + Yi * Yi;
        pxv[ki] = px; pyv[ki] = py;
        psx += px; psy += py;
    }
    red2f(psx, psy, redf);
    float rx = 1.f / ((psx == 0.f) ? 1.f : psx);
    float ry = 1.f / ((psy == 0.f) ? 1.f : psy);

    float ex = 0.f, ey = 0.f;
    #pragma unroll
    for (int ki = 0; ki < 4; ki++) {
        float p0 = pxv[ki] * rx;
        float p1 = pyv[ki] * ry;
        ex = fmaf(p0, logf(p0 + 1e-10f), ex);
        ey = fmaf(p1, logf(p1 + 1e-10f), ey);
    }
    red2f(ex, ey, redf);

    if (tid == 0) {
        float* f = g_feat + (size_t)band * 5 * NROWS;
        f[4 * NROWS + r0] = -ex;
        f[4 * NROWS + r1] = -ey;
    }
}

// ---------------- kernel 2: symmetric correlation GEMM (R11-proven) ----------------
// grid (3, 160). pair 0 -> (0,0), pair 1 -> (1,0), pair 2 -> (1,1). 48x48 tiles.
#define TK 64
#define STRIDE 68
__global__ void __launch_bounds__(128) corr_kernel() {
    const int band = blockIdx.y;
    const int pair = blockIdx.x;
    const int gi = (pair == 0) ? 0 : 1;
    const int gj = (pair == 2) ? 1 : 0;
    const bool offdiag = (pair == 1);

    __shared__ float st[NROWS][STRIDE];
    __shared__ double rinv[NROWS];
    const float* __restrict__ Xb = g_xc + (size_t)band * NROWS * TLEN;

    const int tid = threadIdx.x;
    const int tx = tid & 15;
    const int ty = tid >> 4;
    const int boff = offdiag ? 48 : 0;
    const int nload = offdiag ? 1536 : 768;

    if (tid < NROWS) {
        double n2 = g_norm2[(size_t)band * NROWS + tid];
        double n = sqrt(n2);
        rinv[tid] = (n == 0.0) ? 1.0 : (1.0 / n);
    }

    float hi[6][3], lo[6][3];
    #pragma unroll
    for (int u = 0; u < 6; u++)
        #pragma unroll
        for (int w = 0; w < 3; w++) { hi[u][w] = 0.f; lo[u][w] = 0.f; }

    for (int kt = 0; kt < TLEN; kt += TK) {
        #pragma unroll 1
        for (int idx = tid; idx < nload; idx += 128) {
            int l = idx >> 4, q = idx & 15;
            int gr = (l < 48) ? (gi * 48 + l) : (gj * 48 + (l - 48));
            float4 g = *reinterpret_cast<const float4*>(Xb + (size_t)gr * TLEN + kt + 4 * q);
            *reinterpret_cast<float4*>(&st[l][4 * q]) = g;
        }
        __syncthreads();

        float acc[6][3];
        #pragma unroll
        for (int u = 0; u < 6; u++)
            #pragma unroll
            for (int w = 0; w < 3; w++) acc[u][w] = 0.f;

        #pragma unroll 4
        for (int k4 = 0; k4 < 16; k4++) {
            float4 a4[6], b4[3];
            #pragma unroll
            for (int u = 0; u < 6; u++)
                a4[u] = *reinterpret_cast<const float4*>(&st[ty + 8 * u][4 * k4]);
            #pragma unroll
            for (int w = 0; w < 3; w++)
                b4[w] = *reinterpret_cast<const float4*>(&st[boff + tx + 16 * w][4 * k4]);
            #pragma unroll
            for (int u = 0; u < 6; u++)
                #pragma unroll
                for (int w = 0; w < 3; w++) {
                    acc[u][w] = fmaf(a4[u].x, b4[w].x, acc[u][w]);
                    acc[u][w] = fmaf(a4[u].y, b4[w].y, acc[u][w]);
                    acc[u][w] = fmaf(a4[u].z, b4[w].z, acc[u][w]);
                    acc[u][w] = fmaf(a4[u].w, b4[w].w, acc[u][w]);
                }
        }
        __syncthreads();

        #pragma unroll
        for (int u = 0; u < 6; u++)
            #pragma unroll
            for (int w = 0; w < 3; w++) twosum_acc(hi[u][w], lo[u][w], acc[u][w]);
    }

    float* __restrict__ Cb = g_C + (size_t)band * NROWS * NROWS;
    #pragma unroll
    for (int u = 0; u < 6; u++) {
        int r = gi * 48 + ty + 8 * u;
        double ri = rinv[r];
        #pragma unroll
        for (int w = 0; w < 3; w++) {
            int c = gj * 48 + tx + 16 * w;
            double val = ((double)hi[u][w] + (double)lo[u][w]) * ri * rinv[c];
            float fv = (r == c) ? 0.f : (float)val;
            Cb[r * NROWS + c] = fv;
            if (offdiag) Cb[c * NROWS + r] = fv;
        }
    }
}

// ---------------- kernel 3: radix-select quantile + ballot adjacency + props + MLP ----------------
// grid 160, block 1024  (R12-proven)
__global__ void post_kernel(const int* __restrict__ community,
                            const float* __restrict__ W1, const float* __restrict__ b1,
                            const float* __restrict__ W2, const float* __restrict__ b2,
                            float* __restrict__ outA, float* __restrict__ outF) {
    __shared__ unsigned tril[NTRIL];
    __shared__ unsigned hist[256];
    __shared__ unsigned s_sel[2];
    __shared__ unsigned s_cnt, s_min;
    __shared__ unsigned bits[NROWS][3];
    __shared__ float degf[NROWS];
    __shared__ int comm[NROWS];
    __shared__ float red[32];
    __shared__ float feat11[11];
    __shared__ float h[32];
    __shared__ float sprops[6];
    __shared__ float s_thr;

    const int band = blockIdx.x;
    const int tid = threadIdx.x;
    const int lane = tid & 31;
    const int warp = tid >> 5;
    const float* __restrict__ Cb = g_C + (size_t)band * NROWS * NROWS;
    float* __restrict__ Ao = outA + (size_t)band * NROWS * NROWS;

    for (int idx = tid; idx < NROWS * NROWS; idx += 1024) {
        int i = idx / NROWS, j = idx - i * NROWS;
        if (j < i) tril[i * (i - 1) / 2 + j] = __float_as_uint(fabsf(Cb[idx]));
    }
    if (tid < NROWS) comm[tid] = community[tid];
    if (tid == 0) { s_cnt = 0; s_min = 0xFFFFFFFFu; }
    __syncthreads();

    // ---- exact radix select for rank 3647 (0-based ascending) ----
    unsigned val0;
    {
        int rem = 3647;
        unsigned prefix = 0;
        #pragma unroll 1
        for (int shift = 24; shift >= 0; shift -= 8) {
            for (int i = tid; i < 256; i += 1024) hist[i] = 0;
            __syncthreads();
            unsigned pmask = (shift == 24) ? 0u : (0xFFFFFFFFu << (shift + 8));
            #pragma unroll 1
            for (int i = tid; i < NTRIL; i += 1024) {
                unsigned v = tril[i];
                if ((v & pmask) == prefix) atomicAdd(&hist[(v >> shift) & 255u], 1u);
            }
            __syncthreads();
            if (tid < 32) {
                int base = lane * 8;
                unsigned c[8]; unsigned mysum = 0;
                #pragma unroll
                for (int q = 0; q < 8; q++) { c[q] = hist[base + q]; mysum += c[q]; }
                unsigned incl = mysum;
                #pragma unroll
                for (int o = 1; o < 32; o <<= 1) {
                    unsigned t = __shfl_up_sync(0xffffffffu, incl, o);
                    if (lane >= o) incl += t;
                }
                unsigned excl = incl - mysum;
                bool has = ((unsigned)rem >= excl) && ((unsigned)rem < incl);
                unsigned ball = __ballot_sync(0xffffffffu, has);
                int owner = __ffs(ball) - 1;
                if (lane == owner) {
                    unsigned run = excl;
                    int bucket = 0; unsigned nr = 0;
                    #pragma unroll
                    for (int q = 0; q < 8; q++) {
                        if ((unsigned)rem >= run && (unsigned)rem < run + c[q]) {
                            bucket = base + q; nr = (unsigned)rem - run;
                        }
                        run += c[q];
                    }
                    s_sel[0] = (unsigned)bucket; s_sel[1] = nr;
                }
            }
            __syncthreads();
            prefix |= s_sel[0] << shift;
            rem = (int)s_sel[1];
            __syncthreads();
        }
        val0 = prefix;
    }

    // ---- rank 3648 from one count/min pass ----
    {
        unsigned lc = 0, lm = 0xFFFFFFFFu;
        #pragma unroll 1
        for (int i = tid; i < NTRIL; i += 1024) {
            unsigned v = tril[i];
            if (v <= val0) lc++;
            else lm = min(lm, v);
        }
        #pragma unroll
        for (int o = 16; o > 0; o >>= 1) {
            lc += __shfl_xor_sync(0xffffffffu, lc, o);
            lm = min(lm, __shfl_xor_sync(0xffffffffu, lm, o));
        }
        if (lane == 0) { atomicAdd(&s_cnt, lc); atomicMin(&s_min, lm); }
        __syncthreads();
    }
    if (tid == 0) {
        unsigned val1 = (s_cnt > 3648u) ? val0 : s_min;
        float a  = __uint_as_float(val0);
        float bq = __uint_as_float(val1);
        double pos = 0.8 * (double)(NTRIL - 1);     // 3647.2
        double fr = pos - (double)((int)pos);
        s_thr = (float)((double)a + fr * ((double)bq - (double)a));
    }
    __syncthreads();
    const float thr = s_thr;

    // ---- fused A-write + adjacency bitmasks via warp ballots (32 warps x 3 rows) ----
    #pragma unroll
    for (int rr = 0; rr < 3; rr++) {
        int r = warp * 3 + rr;                // 0..95
        const float* crow = Cb + r * NROWS;
        float c0 = crow[lane];
        float c1 = crow[lane + 32];
        float c2 = crow[lane + 64];
        bool k0 = (fabsf(c0) >= thr) && (lane      != r);
        bool k1 = (fabsf(c1) >= thr) && (lane + 32 != r);
        bool k2 = (fabsf(c2) >= thr) && (lane + 64 != r);
        float* arow = Ao + r * NROWS;
        arow[lane]      = k0 ? c0 : 0.f;
        arow[lane + 32] = k1 ? c1 : 0.f;
        arow[lane + 64] = k2 ? c2 : 0.f;
        unsigned b0 = __ballot_sync(0xffffffffu, k0);
        unsigned b1 = __ballot_sync(0xffffffffu, k1);
        unsigned b2 = __ballot_sync(0xffffffffu, k2);
        if (lane == 0) {
            bits[r][0] = b0; bits[r][1] = b1; bits[r][2] = b2;
            degf[r] = (float)(__popc(b0) + __popc(b1) + __popc(b2));
        }
    }
    __syncthreads();

    int mydeg = (tid < NROWS) ? (int)degf[tid] : 0;

    float degsum = blockReduceSum(tid < NROWS ? (float)mydeg : 0.f, red);
    float ne = 0.5f * degsum;

    float cnt = 0.f;
    if (tid < NROWS) {
        unsigned r0 = bits[tid][0], r1 = bits[tid][1], r2 = bits[tid][2];
        int c6 = 0;
        #pragma unroll 1
        for (int w = 0; w < 3; w++) {
            unsigned mw = bits[tid][w];
            while (mw) {
                int j = __ffs(mw) - 1 + 32 * w;
                mw &= mw - 1;
                c6 += __popc(r0 & bits[j][0]) + __popc(r1 & bits[j][1]) + __popc(r2 & bits[j][2]);
            }
        }
        cnt = (float)c6;
    }
    float tri6 = blockReduceSum(cnt, red);
    float tri = tri6 / 6.0f;

    float pp = (tid < NROWS) ? ((float)mydeg * ((float)mydeg - 1.0f)) : 0.f;
    float poss = blockReduceSum(pp, red) * 0.5f;

    float m2 = 2.0f * ne;
    float m2s = (m2 > 0.f) ? m2 : 1.0f;
    float inv_m2 = 1.0f / m2s;
    float macc = 0.f;
    if (tid < NROWS) {
        int ci = comm[tid];
        float di = (float)mydeg;
        int cntb = 0; float sdeg = 0.f;
        #pragma unroll 2
        for (int j = 0; j < NROWS; j++) {
            if (j != tid && comm[j] == ci) {
                cntb += (int)((bits[tid][j >> 5] >> (j & 31)) & 1u);
                sdeg += degf[j];
            }
        }
        macc = (float)cntb - di * sdeg * inv_m2;
    }
    float modsum = blockReduceSum(macc, red);
    float mod = (m2 > 0.f) ? (modsum * inv_m2) : 0.f;

    if (tid < 5) {
        const float* f = g_feat + (size_t)band * 5 * NROWS + tid * NROWS;
        float sm = 0.f;
        for (int r = 0; r < NROWS; r++) sm += f[r];
        feat11[tid] = sm / (float)NROWS;
    }
    if (tid == 0) {
        float n = (float)NROWS;
        sprops[0] = ne;
        sprops[1] = ne / (n * (n - 1.0f) * 0.5f);
        sprops[2] = degsum / n;
        sprops[3] = (poss > 0.f) ? (tri / poss) : 0.f;
        sprops[4] = (n + 2.0f * ne) / (n * (n - 1.0f));
        sprops[5] = mod;
    }
    __syncthreads();
    if (tid < 6) feat11[5 + tid] = sprops[tid];
    __syncthreads();

    if (tid < 32) {
        float acc = b1[tid];
        #pragma unroll
        for (int k = 0; k < 11; k++) acc = fmaf(feat11[k], W1[tid * 11 + k], acc);
        h[tid] = fmaxf(acc, 0.f);
    }
    __syncthreads();
    if (tid < 64) {
        float acc = b2[tid];
        #pragma unroll
        for (int k = 0; k < 32; k++) acc = fmaf(h[k], W2[tid * 32 + k], acc);
        outF[(size_t)band * 64 + tid] = acc;
    }
}

// ---------------- launch ----------------
extern "C" void kernel_launch(void* const* d_in, const int* in_sizes, int n_in,
                              void* d_out, int out_size) {
    const float* wc        = (const float*)d_in[0];
    const int*   community = (const int*)d_in[2];
    const float* W1        = (const float*)d_in[3];
    const float* b1        = (const float*)d_in[4];
    const float* W2        = (const float*)d_in[5];
    const float* b2        = (const float*)d_in[6];

    float* out = (float*)d_out;
    float* outA = out;                                   // 32*5*96*96
    float* outF = out + (size_t)NBANDS * NROWS * NROWS;  // 32*5*64

    // two no-op launches shift ncu's "-s 5 -c 1" capture window onto stats_fft
    noop_kernel<<<1, 32>>>();
    noop_kernel<<<1, 32>>>();
    init_tw_kernel<<<4, 256>>>();
    dim3 gS(NROWS / 2, NBANDS);
    stats_fft_kernel<<<gS, 256>>>(wc);
    dim3 gC(3, NBANDS);
    corr_kernel<<<gC, 128>>>();
    post_kernel<<<NBANDS, 1024>>>(community, W1, b1, W2, b2, outA, outF);
}

// round 14
// speedup vs baseline: 1.2419x; 1.2419x over previous
#include <cuda_runtime.h>
#include <cuda_bf16.h>
#include <math.h>
#include <stdint.h>

#define NBANDS 160
#define NROWS  96
#define TLEN   2048
#define HALF_T 1024
#define NTRIL  4560   // 96*95/2

// ---------------- scratch (static device globals; no allocation) ----------------
__device__ float  g_xc[(size_t)NBANDS * NROWS * TLEN];    // centered rows (fp32)
__device__ double g_norm2[(size_t)NBANDS * NROWS];        // ||Xc||^2 (exact via df)
__device__ float  g_C[(size_t)NBANDS * NROWS * NROWS];    // correlation matrices
__device__ float  g_feat[(size_t)NBANDS * 5 * NROWS];     // per-row 5 features
__device__ float2 g_tw[HALF_T];                           // exp(-2*pi*i*k/2048)

// ---------------- two-float compensated add (fp32 pipe only) ----------------
__device__ __forceinline__ void twosum_acc(float& hi, float& lo, float a) {
    float s  = hi + a;
    float bb = s - hi;
    float e  = (hi - (s - bb)) + (a - bb);
    hi = s; lo += e;
}

__device__ __forceinline__ float2 cmul(float2 a, float2 b) {
    return make_float2(a.x * b.x - a.y * b.y, a.x * b.y + a.y * b.x);
}

// ---------------- generic fp32 block reduce ----------------
__device__ __forceinline__ float blockReduceSum(float val, float* red) {
    __syncthreads();
    int lane = threadIdx.x & 31, wid = threadIdx.x >> 5;
    #pragma unroll
    for (int o = 16; o > 0; o >>= 1) val += __shfl_xor_sync(0xffffffffu, val, o);
    if (lane == 0) red[wid] = val;
    __syncthreads();
    if (wid == 0) {
        int nw = (blockDim.x + 31) >> 5;
        float v = (lane < nw) ? red[lane] : 0.f;
        #pragma unroll
        for (int o = 16; o > 0; o >>= 1) v += __shfl_xor_sync(0xffffffffu, v, o);
        if (lane == 0) red[0] = v;
    }
    __syncthreads();
    return red[0];
}

// ---------------- batched fp32 reductions for stats kernel (256 thr, 8 warps) ----------------
__device__ __forceinline__ void red4f(float& a, float& b, float& c, float& d, float* buf) {
    int lane = threadIdx.x & 31, wid = threadIdx.x >> 5;
    #pragma unroll
    for (int o = 16; o > 0; o >>= 1) {
        a += __shfl_xor_sync(0xffffffffu, a, o);
        b += __shfl_xor_sync(0xffffffffu, b, o);
        c += __shfl_xor_sync(0xffffffffu, c, o);
        d += __shfl_xor_sync(0xffffffffu, d, o);
    }
    if (lane == 0) { buf[wid*4+0]=a; buf[wid*4+1]=b; buf[wid*4+2]=c; buf[wid*4+3]=d; }
    __syncthreads();
    if (threadIdx.x == 0) {
        float ta=0, tb=0, tc=0, td=0;
        #pragma unroll
        for (int w = 0; w < 8; w++) { ta+=buf[w*4+0]; tb+=buf[w*4+1]; tc+=buf[w*4+2]; td+=buf[w*4+3]; }
        buf[0]=ta; buf[1]=tb; buf[2]=tc; buf[3]=td;
    }
    __syncthreads();
    a=buf[0]; b=buf[1]; c=buf[2]; d=buf[3];
    __syncthreads();
}

__device__ __forceinline__ void red2f(float& a, float& b, float* buf) {
    int lane = threadIdx.x & 31, wid = threadIdx.x >> 5;
    #pragma unroll
    for (int o = 16; o > 0; o >>= 1) {
        a += __shfl_xor_sync(0xffffffffu, a, o);
        b += __shfl_xor_sync(0xffffffffu, b, o);
    }
    if (lane == 0) { buf[wid*2+0]=a; buf[wid*2+1]=b; }
    __syncthreads();
    if (threadIdx.x == 0) {
        float ta=0, tb=0;
        #pragma unroll
        for (int w = 0; w < 8; w++) { ta+=buf[w*2+0]; tb+=buf[w*2+1]; }
        buf[0]=ta; buf[1]=tb;
    }
    __syncthreads();
    a=buf[0]; b=buf[1];
    __syncthreads();
}

__device__ __forceinline__ void redmax2f(float& a, float& b, float* buf) {
    int lane = threadIdx.x & 31, wid = threadIdx.x >> 5;
    #pragma unroll
    for (int o = 16; o > 0; o >>= 1) {
        a = fmaxf(a, __shfl_xor_sync(0xffffffffu, a, o));
        b = fmaxf(b, __shfl_xor_sync(0xffffffffu, b, o));
    }
    if (lane == 0) { buf[wid*2+0]=a; buf[wid*2+1]=b; }
    __syncthreads();
    if (threadIdx.x == 0) {
        float ta=-INFINITY, tb=-INFINITY;
        #pragma unroll
        for (int w = 0; w < 8; w++) { ta=fmaxf(ta,buf[w*2+0]); tb=fmaxf(tb,buf[w*2+1]); }
        buf[0]=ta; buf[1]=tb;
    }
    __syncthreads();
    a=buf[0]; b=buf[1];
    __syncthreads();
}

// df (two-float) reduce for two accumulators
__device__ __forceinline__ void red2df(float& ahi, float& alo, float& bhi, float& blo, float* buf) {
    int lane = threadIdx.x & 31, wid = threadIdx.x >> 5;
    #pragma unroll
    for (int o = 16; o > 0; o >>= 1) {
        float ohi = __shfl_xor_sync(0xffffffffu, ahi, o);
        float olo = __shfl_xor_sync(0xffffffffu, alo, o);
        float s = ahi + ohi; float bb = s - ahi;
        float e = (ahi - (s - bb)) + (ohi - bb);
        alo = alo + olo + e; ahi = s;
        ohi = __shfl_xor_sync(0xffffffffu, bhi, o);
        olo = __shfl_xor_sync(0xffffffffu, blo, o);
        s = bhi + ohi; bb = s - bhi;
        e = (bhi - (s - bb)) + (ohi - bb);
        blo = blo + olo + e; bhi = s;
    }
    if (lane == 0) { buf[wid*4+0]=ahi; buf[wid*4+1]=alo; buf[wid*4+2]=bhi; buf[wid*4+3]=blo; }
    __syncthreads();
    if (threadIdx.x == 0) {
        float thi=0, tlo=0;
        #pragma unroll
        for (int w = 0; w < 8; w++) { twosum_acc(thi, tlo, buf[w*4+0]); tlo += buf[w*4+1]; }
        buf[0]=thi; buf[1]=tlo;
        thi=0; tlo=0;
        #pragma unroll
        for (int w = 0; w < 8; w++) { twosum_acc(thi, tlo, buf[w*4+2]); tlo += buf[w*4+3]; }
        buf[2]=thi; buf[3]=tlo;
    }
    __syncthreads();
    ahi=buf[0]; alo=buf[1]; bhi=buf[2]; blo=buf[3];
    __syncthreads();
}

// ---------------- kernel 0: twiddle table + profiling shim ----------------
__global__ void init_tw_kernel() {
    int k = blockIdx.x * 256 + threadIdx.x;
    if (k < HALF_T) {
        float sv, cv;
        sincospif(-(float)k / 1024.0f, &sv, &cv);
        g_tw[k] = make_float2(cv, sv);
    }
}
__global__ void noop_kernel() {}

// radix-4 Stockham pass at sub-length L (L >= 32 -> conflict-free strided writes).
// Verified butterfly (R9). 512 work items over 256 threads.
template<int LOG2L>
__device__ __forceinline__ void r4_pass(const float2* __restrict__ src,
                                        float2* __restrict__ dst,
                                        const float2* __restrict__ stw,
                                        int tid) {
    const int L = 1 << LOG2L;
    #pragma unroll
    for (int ti = 0; ti < 2; ti++) {
        int t = tid + 256 * ti;
        int j = t & (L - 1);
        int i = t >> LOG2L;
        float2 c0 = src[t];
        float2 c1 = src[t + 512];
        float2 c2 = src[t + 1024];
        float2 c3 = src[t + 1536];
        float2 w  = stw[j << (9  - LOG2L)];
        float2 w2 = stw[j << (10 - LOG2L)];
        float2 c2w = cmul(c2, w2);
        float2 c3w = cmul(c3, w2);
        float2 e0 = make_float2(c0.x + c2w.x, c0.y + c2w.y);
        float2 e1 = make_float2(c0.x - c2w.x, c0.y - c2w.y);
        float2 f0 = make_float2(c1.x + c3w.x, c1.y + c3w.y);
        float2 f1 = make_float2(c1.x - c3w.x, c1.y - c3w.y);
        float2 g0 = cmul(w, f0);
        float2 g1 = cmul(w, f1);
        int o = (i << (LOG2L + 2)) + j;
        dst[o]         = make_float2(e0.x + g0.x, e0.y + g0.y);
        dst[o + L]     = make_float2(e1.x + g1.y, e1.y - g1.x);   // e1 + (-i)g1
        dst[o + 2 * L] = make_float2(e0.x - g0.x, e0.y - g0.y);
        dst[o + 3 * L] = make_float2(e1.x - g1.y, e1.y + g1.x);   // e1 - (-i)g1
    }
}

// ---------------- kernel 1: stats + center + packed 2-row FFT ----------------
// grid (48, 160), block 256. Radix-8 register front-end (padded smem out);
// stage 3, 4 radix-2; pairs (5,6) and (7,8) as radix-4 (conflict-free);
// stage 9 radix-2; stage 10 fused into unpack.
__global__ void stats_fft_kernel(const float* __restrict__ wc) {
    const int rp = blockIdx.x;
    const int band = blockIdx.y;
    const int b = band / 5, nb = band % 5;
    const int r0 = 2 * rp, r1 = r0 + 1;
    const float* __restrict__ x = wc + (((size_t)b * NROWS + r0) * 5 + nb) * TLEN;
    const float* __restrict__ y = wc + (((size_t)b * NROWS + r1) * 5 + nb) * TLEN;

    __shared__ float2 bufA[TLEN + 64];   // padded for radix-8 front-end output
    __shared__ float2 bufB[TLEN];
    __shared__ float2 stw[HALF_T];
    __shared__ float  redf[32];

    const int tid = threadIdx.x;

    #pragma unroll
    for (int i = 0; i < 4; i++) stw[tid + 256 * i] = g_tw[tid + 256 * i];

    float vx[8], vy[8];
    float sx = 0.f, sqx = 0.f, sy = 0.f, sqy = 0.f;
    float mxx = 0.f, mxy = 0.f;
    #pragma unroll
    for (int k = 0; k < 8; k++) {
        float a = x[tid + 256 * k];
        float c = y[tid + 256 * k];
        vx[k] = a; vy[k] = c;
        sx += a; sqx = fmaf(a, a, sqx); mxx = fmaxf(mxx, fabsf(a));
        sy += c; sqy = fmaf(c, c, sqy); mxy = fmaxf(mxy, fabsf(c));
    }

    // ---- fused FFT stages 0+1+2 (radix-8) in registers, padded smem out ----
    {
        float2 A0 = make_float2(vx[0] + vx[4], vy[0] + vy[4]);
        float2 A1 = make_float2(vx[1] + vx[5], vy[1] + vy[5]);
        float2 A2 = make_float2(vx[2] + vx[6], vy[2] + vy[6]);
        float2 A3 = make_float2(vx[3] + vx[7], vy[3] + vy[7]);
        float2 B0 = make_float2(vx[0] - vx[4], vy[0] - vy[4]);
        float2 B1 = make_float2(vx[1] - vx[5], vy[1] - vy[5]);
        float2 B2 = make_float2(vx[2] - vx[6], vy[2] - vy[6]);
        float2 B3 = make_float2(vx[3] - vx[7], vy[3] - vy[7]);
        float2 nB2 = make_float2(B2.y, -B2.x);
        float2 nB3 = make_float2(B3.y, -B3.x);
        float2 P0 = make_float2(A0.x + A2.x,  A0.y + A2.y);
        float2 P2 = make_float2(A0.x - A2.x,  A0.y - A2.y);
        float2 P1 = make_float2(B0.x + nB2.x, B0.y + nB2.y);
        float2 P3 = make_float2(B0.x - nB2.x, B0.y - nB2.y);
        float2 Q0 = make_float2(A1.x + A3.x,  A1.y + A3.y);
        float2 Q2 = make_float2(A1.x - A3.x,  A1.y - A3.y);
        float2 Q1 = make_float2(B1.x + nB3.x, B1.y + nB3.y);
        float2 Q3 = make_float2(B1.x - nB3.x, B1.y - nB3.y);
        const float S2 = 0.70710678118654752440f;
        float2 W1q = make_float2(Q1.x * S2 + Q1.y * S2,  Q1.y * S2 - Q1.x * S2);
        float2 W2q = make_float2(Q2.y, -Q2.x);
        float2 W3q = make_float2(-Q3.x * S2 + Q3.y * S2, -Q3.y * S2 - Q3.x * S2);
        int base = 8 * tid + (tid >> 2);
        bufA[base + 0] = make_float2(P0.x + Q0.x,  P0.y + Q0.y);
        bufA[base + 4] = make_float2(P0.x - Q0.x,  P0.y - Q0.y);
        bufA[base + 1] = make_float2(P1.x + W1q.x, P1.y + W1q.y);
        bufA[base + 5] = make_float2(P1.x - W1q.x, P1.y - W1q.y);
        bufA[base + 2] = make_float2(P2.x + W2q.x, P2.y + W2q.y);
        bufA[base + 6] = make_float2(P2.x - W2q.x, P2.y - W2q.y);
        bufA[base + 3] = make_float2(P3.x + W3q.x, P3.y + W3q.y);
        bufA[base + 7] = make_float2(P3.x - W3q.x, P3.y - W3q.y);
    }

    red4f(sx, sy, sqx, sqy, redf);
    redmax2f(mxx, mxy, redf);
    float meanx = sx / (float)TLEN;
    float meany = sy / (float)TLEN;

    float nxh = 0.f, nxl = 0.f, nyh = 0.f, nyl = 0.f;
    float cx[8], cy[8];
    #pragma unroll
    for (int k = 0; k < 8; k++) {
        cx[k] = vx[k] - meanx; twosum_acc(nxh, nxl, cx[k] * cx[k]);
        cy[k] = vy[k] - meany; twosum_acc(nyh, nyl, cy[k] * cy[k]);
    }
    red2df(nxh, nxl, nyh, nyl, redf);

    float* __restrict__ xc0 = g_xc + ((size_t)band * NROWS + r0) * TLEN;
    float* __restrict__ xc1 = g_xc + ((size_t)band * NROWS + r1) * TLEN;
    #pragma unroll
    for (int k = 0; k < 8; k++) {
        xc0[tid + 256 * k] = cx[k];
        xc1[tid + 256 * k] = cy[k];
    }
    if (tid == 0) {
        double n2x = (double)nxh + (double)nxl;
        double n2y = (double)nyh + (double)nyl;
        g_norm2[(size_t)band * NROWS + r0] = n2x;
        g_norm2[(size_t)band * NROWS + r1] = n2y;
        float* f = g_feat + (size_t)band * 5 * NROWS;
        f[0 * NROWS + r0] = meanx;
        f[1 * NROWS + r0] = (float)sqrt(n2x / (double)(TLEN - 1));
        f[2 * NROWS + r0] = sqx;
        f[3 * NROWS + r0] = mxx;
        f[0 * NROWS + r1] = meany;
        f[1 * NROWS + r1] = (float)sqrt(n2y / (double)(TLEN - 1));
        f[2 * NROWS + r1] = sqy;
        f[3 * NROWS + r1] = mxy;
    }

    // ---- stage 3 (l=8): read padded bufA, write bufB ----
    __syncthreads();
    #pragma unroll
    for (int ti = 0; ti < 4; ti++) {
        int t = tid + 256 * ti;
        int j = t & 7;
        int i = t >> 3;
        float2 u = bufA[t + (t >> 5)];
        float2 v = bufA[t + 1056 + (t >> 5)];
        float2 w = stw[j << 7];
        float vr = v.x * w.x - v.y * w.y;
        float vi = v.x * w.y + v.y * w.x;
        int o = t + i * 8;
        bufB[o]     = make_float2(u.x + vr, u.y + vi);
        bufB[o + 8] = make_float2(u.x - vr, u.y - vi);
    }

    // ---- stage 4 (l=16): bufB -> bufA ----
    __syncthreads();
    #pragma unroll
    for (int ti = 0; ti < 4; ti++) {
        int t = tid + 256 * ti;
        int j = t & 15;
        int i = t >> 4;
        float2 u = bufB[t];
        float2 v = bufB[t + HALF_T];
        float2 w = stw[j << 6];
        float vr = v.x * w.x - v.y * w.y;
        float vi = v.x * w.y + v.y * w.x;
        int o = t + i * 16;
        bufA[o]      = make_float2(u.x + vr, u.y + vi);
        bufA[o + 16] = make_float2(u.x - vr, u.y - vi);
    }

    // ---- radix-4 pair (5,6), L=32: bufA -> bufB (conflict-free) ----
    __syncthreads();
    r4_pass<5>(bufA, bufB, stw, tid);

    // ---- radix-4 pair (7,8), L=128: bufB -> bufA (conflict-free) ----
    __syncthreads();
    r4_pass<7>(bufB, bufA, stw, tid);

    // ---- stage 9 (l=512): bufA -> bufB ----
    __syncthreads();
    #pragma unroll
    for (int ti = 0; ti < 4; ti++) {
        int t = tid + 256 * ti;
        int j = t & 511;
        int i = t >> 9;
        float2 u = bufA[t];
        float2 v = bufA[t + HALF_T];
        float2 w = stw[j << 1];
        float vr = v.x * w.x - v.y * w.y;
        float vi = v.x * w.y + v.y * w.x;
        int o = t + i * 512;
        bufB[o]       = make_float2(u.x + vr, u.y + vi);
        bufB[o + 512] = make_float2(u.x - vr, u.y - vi);
    }
    __syncthreads();
    const float2* src = bufB;

    // ---- fused final stage (s=10) + unpack two real spectra ----
    float psx = 0.f, psy = 0.f;
    float pxv[4], pyv[4];
    #pragma unroll
    for (int ki = 0; ki < 4; ki++) {
        int k = tid + 256 * ki;
        float2 u = src[k];
        float2 v = src[k + 1024];
        float2 w = stw[k];
        float vr = v.x * w.x - v.y * w.y;
        float vi = v.x * w.y + v.y * w.x;
        float2 Zk = make_float2(u.x + vr, u.y + vi);
        float2 Zn;
        if (k == 0) {
            Zn = Zk;
        } else {
            int m = 1024 - k;
            float2 u2 = src[m];
            float2 v2 = src[m + 1024];
            float2 w2 = stw[m];
            float vr2 = v2.x * w2.x - v2.y * w2.y;
            float vi2 = v2.x * w2.y + v2.y * w2.x;
            Zn = make_float2(u2.x - vr2, u2.y - vi2);
        }
        float Xr = 0.5f * (Zk.x + Zn.x);
        float Xi = 0.5f * (Zk.y - Zn.y);
        float Yr = 0.5f * (Zk.y + Zn.y);
        float Yi = 0.5f * (Zn.x - Zk.x);
        float px = Xr * Xr + Xi * Xi;
        float py = Yr * Yr + Yi * Yi;
        pxv[ki] = px; pyv[ki] = py;
        psx += px; psy += py;
    }
    red2f(psx, psy, redf);
    float rx = 1.f / ((psx == 0.f) ? 1.f : psx);
    float ry = 1.f / ((psy == 0.f) ? 1.f : psy);

    float ex = 0.f, ey = 0.f;
    #pragma unroll
    for (int ki = 0; ki < 4; ki++) {
        float p0 = pxv[ki] * rx;
        float p1 = pyv[ki] * ry;
        ex = fmaf(p0, logf(p0 + 1e-10f), ex);
        ey = fmaf(p1, logf(p1 + 1e-10f), ey);
    }
    red2f(ex, ey, redf);

    if (tid == 0) {
        float* f = g_feat + (size_t)band * 5 * NROWS;
        f[4 * NROWS + r0] = -ex;
        f[4 * NROWS + r1] = -ey;
    }
}

// ---------------- kernel 2: symmetric correlation GEMM (R11-proven) ----------------
#define TK 64
#define STRIDE 68
__global__ void __launch_bounds__(128) corr_kernel() {
    const int band = blockIdx.y;
    const int pair = blockIdx.x;
    const int gi = (pair == 0) ? 0 : 1;
    const int gj = (pair == 2) ? 1 : 0;
    const bool offdiag = (pair == 1);

    __shared__ float st[NROWS][STRIDE];
    __shared__ double rinv[NROWS];
    const float* __restrict__ Xb = g_xc + (size_t)band * NROWS * TLEN;

    const int tid = threadIdx.x;
    const int tx = tid & 15;
    const int ty = tid >> 4;
    const int boff = offdiag ? 48 : 0;
    const int nload = offdiag ? 1536 : 768;

    if (tid < NROWS) {
        double n2 = g_norm2[(size_t)band * NROWS + tid];
        double n = sqrt(n2);
        rinv[tid] = (n == 0.0) ? 1.0 : (1.0 / n);
    }

    float hi[6][3], lo[6][3];
    #pragma unroll
    for (int u = 0; u < 6; u++)
        #pragma unroll
        for (int w = 0; w < 3; w++) { hi[u][w] = 0.f; lo[u][w] = 0.f; }

    for (int kt = 0; kt < TLEN; kt += TK) {
        #pragma unroll 1
        for (int idx = tid; idx < nload; idx += 128) {
            int l = idx >> 4, q = idx & 15;
            int gr = (l < 48) ? (gi * 48 + l) : (gj * 48 + (l - 48));
            float4 g = *reinterpret_cast<const float4*>(Xb + (size_t)gr * TLEN + kt + 4 * q);
            *reinterpret_cast<float4*>(&st[l][4 * q]) = g;
        }
        __syncthreads();

        float acc[6][3];
        #pragma unroll
        for (int u = 0; u < 6; u++)
            #pragma unroll
            for (int w = 0; w < 3; w++) acc[u][w] = 0.f;

        #pragma unroll 4
        for (int k4 = 0; k4 < 16; k4++) {
            float4 a4[6], b4[3];
            #pragma unroll
            for (int u = 0; u < 6; u++)
                a4[u] = *reinterpret_cast<const float4*>(&st[ty + 8 * u][4 * k4]);
            #pragma unroll
            for (int w = 0; w < 3; w++)
                b4[w] = *reinterpret_cast<const float4*>(&st[boff + tx + 16 * w][4 * k4]);
            #pragma unroll
            for (int u = 0; u < 6; u++)
                #pragma unroll
                for (int w = 0; w < 3; w++) {
                    acc[u][w] = fmaf(a4[u].x, b4[w].x, acc[u][w]);
                    acc[u][w] = fmaf(a4[u].y, b4[w].y, acc[u][w]);
                    acc[u][w] = fmaf(a4[u].z, b4[w].z, acc[u][w]);
                    acc[u][w] = fmaf(a4[u].w, b4[w].w, acc[u][w]);
                }
        }
        __syncthreads();

        #pragma unroll
        for (int u = 0; u < 6; u++)
            #pragma unroll
            for (int w = 0; w < 3; w++) twosum_acc(hi[u][w], lo[u][w], acc[u][w]);
    }

    float* __restrict__ Cb = g_C + (size_t)band * NROWS * NROWS;
    #pragma unroll
    for (int u = 0; u < 6; u++) {
        int r = gi * 48 + ty + 8 * u;
        double ri = rinv[r];
        #pragma unroll
        for (int w = 0; w < 3; w++) {
            int c = gj * 48 + tx + 16 * w;
            double val = ((double)hi[u][w] + (double)lo[u][w]) * ri * rinv[c];
            float fv = (r == c) ? 0.f : (float)val;
            Cb[r * NROWS + c] = fv;
            if (offdiag) Cb[c * NROWS + r] = fv;
        }
    }
}

// ---------------- kernel 3: radix-select quantile + ballot adjacency + props + MLP ----------------
__global__ void post_kernel(const int* __restrict__ community,
                            const float* __restrict__ W1, const float* __restrict__ b1,
                            const float* __restrict__ W2, const float* __restrict__ b2,
                            float* __restrict__ outA, float* __restrict__ outF) {
    __shared__ unsigned tril[NTRIL];
    __shared__ unsigned hist[256];
    __shared__ unsigned s_sel[2];
    __shared__ unsigned s_cnt, s_min;
    __shared__ unsigned bits[NROWS][3];
    __shared__ float degf[NROWS];
    __shared__ int comm[NROWS];
    __shared__ float red[32];
    __shared__ float feat11[11];
    __shared__ float h[32];
    __shared__ float sprops[6];
    __shared__ float s_thr;

    const int band = blockIdx.x;
    const int tid = threadIdx.x;
    const int lane = tid & 31;
    const int warp = tid >> 5;
    const float* __restrict__ Cb = g_C + (size_t)band * NROWS * NROWS;
    float* __restrict__ Ao = outA + (size_t)band * NROWS * NROWS;

    for (int idx = tid; idx < NROWS * NROWS; idx += 1024) {
        int i = idx / NROWS, j = idx - i * NROWS;
        if (j < i) tril[i * (i - 1) / 2 + j] = __float_as_uint(fabsf(Cb[idx]));
    }
    if (tid < NROWS) comm[tid] = community[tid];
    if (tid == 0) { s_cnt = 0; s_min = 0xFFFFFFFFu; }
    __syncthreads();

    unsigned val0;
    {
        int rem = 3647;
        unsigned prefix = 0;
        #pragma unroll 1
        for (int shift = 24; shift >= 0; shift -= 8) {
            for (int i = tid; i < 256; i += 1024) hist[i] = 0;
            __syncthreads();
            unsigned pmask = (shift == 24) ? 0u : (0xFFFFFFFFu << (shift + 8));
            #pragma unroll 1
            for (int i = tid; i < NTRIL; i += 1024) {
                unsigned v = tril[i];
                if ((v & pmask) == prefix) atomicAdd(&hist[(v >> shift) & 255u], 1u);
            }
            __syncthreads();
            if (tid < 32) {
                int base = lane * 8;
                unsigned c[8]; unsigned mysum = 0;
                #pragma unroll
                for (int q = 0; q < 8; q++) { c[q] = hist[base + q]; mysum += c[q]; }
                unsigned incl = mysum;
                #pragma unroll
                for (int o = 1; o < 32; o <<= 1) {
                    unsigned t = __shfl_up_sync(0xffffffffu, incl, o);
                    if (lane >= o) incl += t;
                }
                unsigned excl = incl - mysum;
                bool has = ((unsigned)rem >= excl) && ((unsigned)rem < incl);
                unsigned ball = __ballot_sync(0xffffffffu, has);
                int owner = __ffs(ball) - 1;
                if (lane == owner) {
                    unsigned run = excl;
                    int bucket = 0; unsigned nr = 0;
                    #pragma unroll
                    for (int q = 0; q < 8; q++) {
                        if ((unsigned)rem >= run && (unsigned)rem < run + c[q]) {
                            bucket = base + q; nr = (unsigned)rem - run;
                        }
                        run += c[q];
                    }
                    s_sel[0] = (unsigned)bucket; s_sel[1] = nr;
                }
            }
            __syncthreads();
            prefix |= s_sel[0] << shift;
            rem = (int)s_sel[1];
            __syncthreads();
        }
        val0 = prefix;
    }

    {
        unsigned lc = 0, lm = 0xFFFFFFFFu;
        #pragma unroll 1
        for (int i = tid; i < NTRIL; i += 1024) {
            unsigned v = tril[i];
            if (v <= val0) lc++;
            else lm = min(lm, v);
        }
        #pragma unroll
        for (int o = 16; o > 0; o >>= 1) {
            lc += __shfl_xor_sync(0xffffffffu, lc, o);
            lm = min(lm, __shfl_xor_sync(0xffffffffu, lm, o));
        }
        if (lane == 0) { atomicAdd(&s_cnt, lc); atomicMin(&s_min, lm); }
        __syncthreads();
    }
    if (tid == 0) {
        unsigned val1 = (s_cnt > 3648u) ? val0 : s_min;
        float a  = __uint_as_float(val0);
        float bq = __uint_as_float(val1);
        double pos = 0.8 * (double)(NTRIL - 1);
        double fr = pos - (double)((int)pos);
        s_thr = (float)((double)a + fr * ((double)bq - (double)a));
    }
    __syncthreads();
    const float thr = s_thr;

    #pragma unroll
    for (int rr = 0; rr < 3; rr++) {
        int r = warp * 3 + rr;
        const float* crow = Cb + r * NROWS;
        float c0 = crow[lane];
        float c1 = crow[lane + 32];
        float c2 = crow[lane + 64];
        bool k0 = (fabsf(c0) >= thr) && (lane      != r);
        bool k1 = (fabsf(c1) >= thr) && (lane + 32 != r);
        bool k2 = (fabsf(c2) >= thr) && (lane + 64 != r);
        float* arow = Ao + r * NROWS;
        arow[lane]      = k0 ? c0 : 0.f;
        arow[lane + 32] = k1 ? c1 : 0.f;
        arow[lane + 64] = k2 ? c2 : 0.f;
        unsigned b0 = __ballot_sync(0xffffffffu, k0);
        unsigned b1 = __ballot_sync(0xffffffffu, k1);
        unsigned b2 = __ballot_sync(0xffffffffu, k2);
        if (lane == 0) {
            bits[r][0] = b0; bits[r][1] = b1; bits[r][2] = b2;
            degf[r] = (float)(__popc(b0) + __popc(b1) + __popc(b2));
        }
    }
    __syncthreads();

    int mydeg = (tid < NROWS) ? (int)degf[tid] : 0;

    float degsum = blockReduceSum(tid < NROWS ? (float)mydeg : 0.f, red);
    float ne = 0.5f * degsum;

    float cnt = 0.f;
    if (tid < NROWS) {
        unsigned r0 = bits[tid][0], r1 = bits[tid][1], r2 = bits[tid][2];
        int c6 = 0;
        #pragma unroll 1
        for (int w = 0; w < 3; w++) {
            unsigned mw = bits[tid][w];
            while (mw) {
                int j = __ffs(mw) - 1 + 32 * w;
                mw &= mw - 1;
                c6 += __popc(r0 & bits[j][0]) + __popc(r1 & bits[j][1]) + __popc(r2 & bits[j][2]);
            }
        }
        cnt = (float)c6;
    }
    float tri6 = blockReduceSum(cnt, red);
    float tri = tri6 / 6.0f;

    float pp = (tid < NROWS) ? ((float)mydeg * ((float)mydeg - 1.0f)) : 0.f;
    float poss = blockReduceSum(pp, red) * 0.5f;

    float m2 = 2.0f * ne;
    float m2s = (m2 > 0.f) ? m2 : 1.0f;
    float inv_m2 = 1.0f / m2s;
    float macc = 0.f;
    if (tid < NROWS) {
        int ci = comm[tid];
        float di = (float)mydeg;
        int cntb = 0; float sdeg = 0.f;
        #pragma unroll 2
        for (int j = 0; j < NROWS; j++) {
            if (j != tid && comm[j] == ci) {
                cntb += (int)((bits[tid][j >> 5] >> (j & 31)) & 1u);
                sdeg += degf[j];
            }
        }
        macc = (float)cntb - di * sdeg * inv_m2;
    }
    float modsum = blockReduceSum(macc, red);
    float mod = (m2 > 0.f) ? (modsum * inv_m2) : 0.f;

    if (tid < 5) {
        const float* f = g_feat + (size_t)band * 5 * NROWS + tid * NROWS;
        float sm = 0.f;
        for (int r = 0; r < NROWS; r++) sm += f[r];
        feat11[tid] = sm / (float)NROWS;
    }
    if (tid == 0) {
        float n = (float)NROWS;
        sprops[0] = ne;
        sprops[1] = ne / (n * (n - 1.0f) * 0.5f);
        sprops[2] = degsum / n;
        sprops[3] = (poss > 0.f) ? (tri / poss) : 0.f;
        sprops[4] = (n + 2.0f * ne) / (n * (n - 1.0f));
        sprops[5] = mod;
    }
    __syncthreads();
    if (tid < 6) feat11[5 + tid] = sprops[tid];
    __syncthreads();

    if (tid < 32) {
        float acc = b1[tid];
        #pragma unroll
        for (int k = 0; k < 11; k++) acc = fmaf(feat11[k], W1[tid * 11 + k], acc);
        h[tid] = fmaxf(acc, 0.f);
    }
    __syncthreads();
    if (tid < 64) {
        float acc = b2[tid];
        #pragma unroll
        for (int k = 0; k < 32; k++) acc = fmaf(h[k], W2[tid * 32 + k], acc);
        outF[(size_t)band * 64 + tid] = acc;
    }
}

// ---------------- launch ----------------
extern "C" void kernel_launch(void* const* d_in, const int* in_sizes, int n_in,
                              void* d_out, int out_size) {
    const float* wc        = (const float*)d_in[0];
    const int*   community = (const int*)d_in[2];
    const float* W1        = (const float*)d_in[3];
    const float* b1        = (const float*)d_in[4];
    const float* W2        = (const float*)d_in[5];
    const float* b2        = (const float*)d_in[6];

    float* out = (float*)d_out;
    float* outA = out;                                   // 32*5*96*96
    float* outF = out + (size_t)NBANDS * NROWS * NROWS;  // 32*5*64

    // one noop: shifts the ncu capture window so corr_kernel (4th launch) is profiled
    noop_kernel<<<1, 32>>>();
    init_tw_kernel<<<4, 256>>>();
    dim3 gS(NROWS / 2, NBANDS);
    stats_fft_kernel<<<gS, 256>>>(wc);
    dim3 gC(3, NBANDS);
    corr_kernel<<<gC, 128>>>();
    post_kernel<<<NBANDS, 1024>>>(community, W1, b1, W2, b2, outA, outF);
}